// round 1
// baseline (speedup 1.0000x reference)
#include <cuda_runtime.h>
#include <math.h>
#include <stdint.h>

// Problem shape (fixed by reference): B=2, C=512, H=W=64 -> N=4096, 32 groups.
#define BATCH 2
#define CCH   512
#define NGRP  32
#define NPIX  4096
#define EPSV  1e-6f

// ---------------------------------------------------------------------------
// Scratch (static __device__ arrays; no allocations allowed)
// ---------------------------------------------------------------------------
__device__ float g_h [BATCH * CCH * NPIX];        // groupnorm output
__device__ float g_q [BATCH * CCH * NPIX];
__device__ float g_k [BATCH * CCH * NPIX];
__device__ float g_v [BATCH * CCH * NPIX];
__device__ float g_s [(size_t)BATCH * NPIX * NPIX]; // scores / attn (in-place softmax)
__device__ float g_ao[BATCH * CCH * NPIX];        // attention output (pre out-proj)

// ---------------------------------------------------------------------------
// Reductions
// ---------------------------------------------------------------------------
__device__ __forceinline__ float warpSum(float v) {
    #pragma unroll
    for (int o = 16; o; o >>= 1) v += __shfl_xor_sync(0xffffffffu, v, o);
    return v;
}
__device__ __forceinline__ float warpMax(float v) {
    #pragma unroll
    for (int o = 16; o; o >>= 1) v = fmaxf(v, __shfl_xor_sync(0xffffffffu, v, o));
    return v;
}

// ---------------------------------------------------------------------------
// GroupNorm: one block per (batch, group). 16 ch * 4096 px = 65536 floats.
// ---------------------------------------------------------------------------
__global__ __launch_bounds__(256) void groupnorm_kernel(
    const float* __restrict__ x, const float* __restrict__ w,
    const float* __restrict__ b, float* __restrict__ out)
{
    const int CPG = CCH / NGRP;          // 16
    const int GSZ = CPG * NPIX;          // 65536
    int bg = blockIdx.x;
    int batch = bg / NGRP, g = bg % NGRP;
    size_t base = (size_t)batch * CCH * NPIX + (size_t)g * CPG * NPIX;
    const float4* x4 = (const float4*)(x + base);
    float4* o4 = (float4*)(out + base);
    int tid = threadIdx.x;

    float s = 0.f, ss = 0.f;
    for (int i = tid; i < GSZ / 4; i += 256) {
        float4 v = x4[i];
        s  += v.x + v.y + v.z + v.w;
        ss += v.x * v.x + v.y * v.y + v.z * v.z + v.w * v.w;
    }
    __shared__ float rs[8], rss[8];
    float ws = warpSum(s), wss = warpSum(ss);
    int lane = tid & 31, wid = tid >> 5;
    if (lane == 0) { rs[wid] = ws; rss[wid] = wss; }
    __syncthreads();
    __shared__ float s_mean, s_inv;
    if (tid == 0) {
        float S = 0.f, SS = 0.f;
        #pragma unroll
        for (int i = 0; i < 8; i++) { S += rs[i]; SS += rss[i]; }
        float mean = S / (float)GSZ;
        float var = SS / (float)GSZ - mean * mean;
        s_mean = mean;
        s_inv = rsqrtf(var + EPSV);
    }
    __syncthreads();
    float mean = s_mean, inv = s_inv;

    for (int i = tid; i < GSZ / 4; i += 256) {
        int c = g * CPG + ((i * 4) / NPIX);   // all 4 elems in same channel
        float sc = w[c] * inv;
        float sb = b[c] - mean * sc;
        float4 v = x4[i];
        v.x = v.x * sc + sb; v.y = v.y * sc + sb;
        v.z = v.z * sc + sb; v.w = v.w * sc + sb;
        o4[i] = v;
    }
}

// ---------------------------------------------------------------------------
// Row softmax over 4096 cols, in place. One block per row, 16 floats/thread.
// ---------------------------------------------------------------------------
__global__ __launch_bounds__(256) void softmax_kernel(float* __restrict__ s)
{
    size_t row = blockIdx.x;
    float4* p = (float4*)(s + row * NPIX);
    int tid = threadIdx.x;
    float4 r[4];
    float m = -1e30f;
    #pragma unroll
    for (int i = 0; i < 4; i++) {
        r[i] = p[tid + i * 256];
        m = fmaxf(m, fmaxf(fmaxf(r[i].x, r[i].y), fmaxf(r[i].z, r[i].w)));
    }
    __shared__ float red[8];
    float wm = warpMax(m);
    int lane = tid & 31, wid = tid >> 5;
    if (lane == 0) red[wid] = wm;
    __syncthreads();
    __shared__ float s_m, s_inv;
    if (tid == 0) {
        float mm = red[0];
        #pragma unroll
        for (int i = 1; i < 8; i++) mm = fmaxf(mm, red[i]);
        s_m = mm;
    }
    __syncthreads();
    m = s_m;
    float sum = 0.f;
    #pragma unroll
    for (int i = 0; i < 4; i++) {
        r[i].x = expf(r[i].x - m); r[i].y = expf(r[i].y - m);
        r[i].z = expf(r[i].z - m); r[i].w = expf(r[i].w - m);
        sum += r[i].x + r[i].y + r[i].z + r[i].w;
    }
    float wsum = warpSum(sum);
    if (lane == 0) red[wid] = wsum;
    __syncthreads();
    if (tid == 0) {
        float S = 0.f;
        #pragma unroll
        for (int i = 0; i < 8; i++) S += red[i];
        s_inv = 1.f / S;
    }
    __syncthreads();
    float inv = s_inv;
    #pragma unroll
    for (int i = 0; i < 4; i++) {
        r[i].x *= inv; r[i].y *= inv; r[i].z *= inv; r[i].w *= inv;
        p[tid + i * 256] = r[i];
    }
}

// ---------------------------------------------------------------------------
// Generic SGEMM: C[m,n] = alpha * sum_k A(m,k)*B(k,n)  (+bias[m]) (+resid)
//   TA==0: A(m,k) = A[m*lda + k]     TA==1: A(m,k) = A[k*lda + m]
//   TB==0: B(k,n) = B[k*ldb + n]     TB==1: B(k,n) = B[n*ldb + k]
// Block tile 128x128, k-tile 16, 256 threads, 8x8 per thread.
// blockIdx.z = batch, per-operand batch strides.
// ---------------------------------------------------------------------------
#define TM 128
#define TN 128
#define TK 16

template<int TA, int TB, bool BIAS, bool RES>
__global__ __launch_bounds__(256) void sgemm_kernel(
    const float* __restrict__ A, int lda, size_t sA,
    const float* __restrict__ B, int ldb, size_t sB,
    float* __restrict__ C, int ldc, size_t sC,
    const float* __restrict__ bias,
    const float* __restrict__ resid, size_t sR,
    int K, float alpha)
{
    __shared__ float As[TK][TM];
    __shared__ float Bs[TK][TN];

    int bz = blockIdx.z;
    A += (size_t)bz * sA;
    B += (size_t)bz * sB;
    C += (size_t)bz * sC;
    if (RES) resid += (size_t)bz * sR;

    const int m0 = blockIdx.y * TM;
    const int n0 = blockIdx.x * TN;
    const int tid = threadIdx.x;
    const int tm = (tid >> 4) << 3;   // 0..120
    const int tn = (tid & 15) << 3;   // 0..120

    float acc[8][8];
    #pragma unroll
    for (int i = 0; i < 8; i++)
        #pragma unroll
        for (int j = 0; j < 8; j++) acc[i][j] = 0.f;

    for (int k0 = 0; k0 < K; k0 += TK) {
        // ---- load A tile into As[k][m] ----
        if (TA == 0) {
            #pragma unroll
            for (int t = 0; t < 2; t++) {
                int f = tid * 2 + t;                 // 0..511 float4s
                int mm = f >> 2, k4 = (f & 3) << 2;
                float4 v = *(const float4*)(A + (size_t)(m0 + mm) * lda + k0 + k4);
                As[k4 + 0][mm] = v.x; As[k4 + 1][mm] = v.y;
                As[k4 + 2][mm] = v.z; As[k4 + 3][mm] = v.w;
            }
        } else {
            #pragma unroll
            for (int t = 0; t < 2; t++) {
                int f = tid * 2 + t;
                int kk = f >> 5, mm4 = (f & 31) << 2;
                *(float4*)&As[kk][mm4] =
                    *(const float4*)(A + (size_t)(k0 + kk) * lda + m0 + mm4);
            }
        }
        // ---- load B tile into Bs[k][n] ----
        if (TB == 0) {
            #pragma unroll
            for (int t = 0; t < 2; t++) {
                int f = tid * 2 + t;
                int kk = f >> 5, nn4 = (f & 31) << 2;
                *(float4*)&Bs[kk][nn4] =
                    *(const float4*)(B + (size_t)(k0 + kk) * ldb + n0 + nn4);
            }
        } else {
            #pragma unroll
            for (int t = 0; t < 2; t++) {
                int f = tid * 2 + t;
                int nn = f >> 2, k4 = (f & 3) << 2;
                float4 v = *(const float4*)(B + (size_t)(n0 + nn) * ldb + k0 + k4);
                Bs[k4 + 0][nn] = v.x; Bs[k4 + 1][nn] = v.y;
                Bs[k4 + 2][nn] = v.z; Bs[k4 + 3][nn] = v.w;
            }
        }
        __syncthreads();

        #pragma unroll
        for (int kk = 0; kk < TK; kk++) {
            float a[8], bb[8];
            *(float4*)(a)     = *(float4*)&As[kk][tm];
            *(float4*)(a + 4) = *(float4*)&As[kk][tm + 4];
            *(float4*)(bb)     = *(float4*)&Bs[kk][tn];
            *(float4*)(bb + 4) = *(float4*)&Bs[kk][tn + 4];
            #pragma unroll
            for (int i = 0; i < 8; i++)
                #pragma unroll
                for (int j = 0; j < 8; j++)
                    acc[i][j] = fmaf(a[i], bb[j], acc[i][j]);
        }
        __syncthreads();
    }

    // ---- epilogue ----
    #pragma unroll
    for (int i = 0; i < 8; i++) {
        int m = m0 + tm + i;
        float bi = BIAS ? bias[m] : 0.f;
        #pragma unroll
        for (int j = 0; j < 8; j += 4) {
            float4 o;
            o.x = acc[i][j + 0] * alpha + bi;
            o.y = acc[i][j + 1] * alpha + bi;
            o.z = acc[i][j + 2] * alpha + bi;
            o.w = acc[i][j + 3] * alpha + bi;
            size_t off = (size_t)m * ldc + n0 + tn + j;
            if (RES) {
                float4 r = *(const float4*)(resid + off);
                o.x += r.x; o.y += r.y; o.z += r.z; o.w += r.w;
            }
            *(float4*)(C + off) = o;
        }
    }
}

// ---------------------------------------------------------------------------
// Host launcher
// ---------------------------------------------------------------------------
extern "C" void kernel_launch(void* const* d_in, const int* in_sizes, int n_in,
                              void* d_out, int out_size)
{
    const float* x      = (const float*)d_in[0];
    const float* norm_w = (const float*)d_in[1];
    const float* norm_b = (const float*)d_in[2];
    const float* wq     = (const float*)d_in[3];
    const float* bq     = (const float*)d_in[4];
    const float* wk     = (const float*)d_in[5];
    const float* bk     = (const float*)d_in[6];
    const float* wv     = (const float*)d_in[7];
    const float* bv     = (const float*)d_in[8];
    const float* wo     = (const float*)d_in[9];
    const float* bo     = (const float*)d_in[10];
    float* out = (float*)d_out;

    float *h, *q, *k, *v, *s, *ao;
    cudaGetSymbolAddress((void**)&h,  g_h);
    cudaGetSymbolAddress((void**)&q,  g_q);
    cudaGetSymbolAddress((void**)&k,  g_k);
    cudaGetSymbolAddress((void**)&v,  g_v);
    cudaGetSymbolAddress((void**)&s,  g_s);
    cudaGetSymbolAddress((void**)&ao, g_ao);

    const size_t CN = (size_t)CCH * NPIX;     // per-batch [C,N] stride
    const size_t NN = (size_t)NPIX * NPIX;    // per-batch [N,N] stride
    const float scale = 1.0f / sqrtf((float)CCH);

    // 1. GroupNorm
    groupnorm_kernel<<<BATCH * NGRP, 256>>>(x, norm_w, norm_b, h);

    // 2. q/k/v projections: [512,512] x [512,4096] per batch
    dim3 gProj(NPIX / TN, CCH / TM, BATCH);
    sgemm_kernel<0, 0, true, false><<<gProj, 256>>>(
        wq, CCH, 0, h, NPIX, CN, q, NPIX, CN, bq, nullptr, 0, CCH, 1.0f);
    sgemm_kernel<0, 0, true, false><<<gProj, 256>>>(
        wk, CCH, 0, h, NPIX, CN, k, NPIX, CN, bk, nullptr, 0, CCH, 1.0f);
    sgemm_kernel<0, 0, true, false><<<gProj, 256>>>(
        wv, CCH, 0, h, NPIX, CN, v, NPIX, CN, bv, nullptr, 0, CCH, 1.0f);

    // 3. scores[i,j] = scale * sum_c q[c,i] k[c,j]   (TN gemm, M=N=4096, K=512)
    dim3 gScore(NPIX / TN, NPIX / TM, BATCH);
    sgemm_kernel<1, 0, false, false><<<gScore, 256>>>(
        q, NPIX, CN, k, NPIX, CN, s, NPIX, NN, nullptr, nullptr, 0, CCH, scale);

    // 4. softmax over rows (in place)
    softmax_kernel<<<BATCH * NPIX, 256>>>(s);

    // 5. ao[c,i] = sum_j v[c,j] attn[i,j]   (NT gemm, M=512, N=4096, K=4096)
    dim3 gOut(NPIX / TN, CCH / TM, BATCH);
    sgemm_kernel<0, 1, false, false><<<gOut, 256>>>(
        v, NPIX, CN, s, NPIX, NN, ao, NPIX, CN, nullptr, nullptr, 0, NPIX, 1.0f);

    // 6. final: out = x + wo @ ao + bo
    sgemm_kernel<0, 0, true, true><<<gOut, 256>>>(
        wo, CCH, 0, ao, NPIX, CN, out, NPIX, CN, bo, x, CN, CCH, 1.0f);
}

// round 3
// speedup vs baseline: 2.3207x; 2.3207x over previous
#include <cuda_runtime.h>
#include <math.h>
#include <stdint.h>

// Shape fixed by reference: B=2, C=512, H=W=64 -> N=4096, 32 groups.
#define BATCH 2
#define CCH   512
#define NGRP  32
#define NPIX  4096
#define EPSV  1e-6f

// ---------------------------------------------------------------------------
// Scratch
// ---------------------------------------------------------------------------
__device__ float g_h [BATCH * CCH * NPIX];
__device__ float g_q [BATCH * CCH * NPIX];
__device__ float g_k [BATCH * CCH * NPIX];
__device__ float g_v [BATCH * CCH * NPIX];
__device__ float g_s [(size_t)BATCH * NPIX * NPIX];
__device__ float g_ao[BATCH * CCH * NPIX];

// ---------------------------------------------------------------------------
// Helpers
// ---------------------------------------------------------------------------
__device__ __forceinline__ float warpSum(float v) {
    #pragma unroll
    for (int o = 16; o; o >>= 1) v += __shfl_xor_sync(0xffffffffu, v, o);
    return v;
}
__device__ __forceinline__ float warpMax(float v) {
    #pragma unroll
    for (int o = 16; o; o >>= 1) v = fmaxf(v, __shfl_xor_sync(0xffffffffu, v, o));
    return v;
}
__device__ __forceinline__ uint32_t f2tf(float f) {
    uint32_t u;
    asm("cvt.rna.tf32.f32 %0, %1;" : "=r"(u) : "f"(f));
    return u;
}

// ---------------------------------------------------------------------------
// GroupNorm: one block per (batch, group). 16 ch * 4096 px = 65536 floats.
// ---------------------------------------------------------------------------
__global__ __launch_bounds__(256) void groupnorm_kernel(
    const float* __restrict__ x, const float* __restrict__ w,
    const float* __restrict__ b, float* __restrict__ out)
{
    const int CPG = CCH / NGRP;
    const int GSZ = CPG * NPIX;
    int bg = blockIdx.x;
    int batch = bg / NGRP, g = bg % NGRP;
    size_t base = (size_t)batch * CCH * NPIX + (size_t)g * CPG * NPIX;
    const float4* x4 = (const float4*)(x + base);
    float4* o4 = (float4*)(out + base);
    int tid = threadIdx.x;

    float s = 0.f, ss = 0.f;
    for (int i = tid; i < GSZ / 4; i += 256) {
        float4 v = x4[i];
        s  += v.x + v.y + v.z + v.w;
        ss += v.x * v.x + v.y * v.y + v.z * v.z + v.w * v.w;
    }
    __shared__ float rs[8], rss[8];
    float ws = warpSum(s), wss = warpSum(ss);
    int lane = tid & 31, wid = tid >> 5;
    if (lane == 0) { rs[wid] = ws; rss[wid] = wss; }
    __syncthreads();
    __shared__ float s_mean, s_inv;
    if (tid == 0) {
        float S = 0.f, SS = 0.f;
        #pragma unroll
        for (int i = 0; i < 8; i++) { S += rs[i]; SS += rss[i]; }
        float mean = S / (float)GSZ;
        float var = SS / (float)GSZ - mean * mean;
        s_mean = mean;
        s_inv = rsqrtf(var + EPSV);
    }
    __syncthreads();
    float mean = s_mean, inv = s_inv;

    for (int i = tid; i < GSZ / 4; i += 256) {
        int c = g * CPG + ((i * 4) / NPIX);
        float sc = w[c] * inv;
        float sb = b[c] - mean * sc;
        float4 v = x4[i];
        v.x = v.x * sc + sb; v.y = v.y * sc + sb;
        v.z = v.z * sc + sb; v.w = v.w * sc + sb;
        o4[i] = v;
    }
}

// ---------------------------------------------------------------------------
// Row softmax over 4096 cols, in place. One block per row.
// ---------------------------------------------------------------------------
__global__ __launch_bounds__(256) void softmax_kernel(float* __restrict__ s)
{
    size_t row = blockIdx.x;
    float4* p = (float4*)(s + row * NPIX);
    int tid = threadIdx.x;
    float4 r[4];
    float m = -1e30f;
    #pragma unroll
    for (int i = 0; i < 4; i++) {
        r[i] = p[tid + i * 256];
        m = fmaxf(m, fmaxf(fmaxf(r[i].x, r[i].y), fmaxf(r[i].z, r[i].w)));
    }
    __shared__ float red[8];
    float wm = warpMax(m);
    int lane = tid & 31, wid = tid >> 5;
    if (lane == 0) red[wid] = wm;
    __syncthreads();
    __shared__ float s_m, s_inv;
    if (tid == 0) {
        float mm = red[0];
        #pragma unroll
        for (int i = 1; i < 8; i++) mm = fmaxf(mm, red[i]);
        s_m = mm;
    }
    __syncthreads();
    m = s_m;
    float sum = 0.f;
    #pragma unroll
    for (int i = 0; i < 4; i++) {
        r[i].x = expf(r[i].x - m); r[i].y = expf(r[i].y - m);
        r[i].z = expf(r[i].z - m); r[i].w = expf(r[i].w - m);
        sum += r[i].x + r[i].y + r[i].z + r[i].w;
    }
    float wsum = warpSum(sum);
    if (lane == 0) red[wid] = wsum;
    __syncthreads();
    if (tid == 0) {
        float S = 0.f;
        #pragma unroll
        for (int i = 0; i < 8; i++) S += red[i];
        s_inv = 1.f / S;
    }
    __syncthreads();
    float inv = s_inv;
    #pragma unroll
    for (int i = 0; i < 4; i++) {
        r[i].x *= inv; r[i].y *= inv; r[i].z *= inv; r[i].w *= inv;
        p[tid + i * 256] = r[i];
    }
}

// ---------------------------------------------------------------------------
// TF32 tensor-core GEMM:
//   C[m,n] = alpha * sum_k A(m,k)*B(k,n)  (+bias[m]) (+resid)
//   TA==0: A(m,k)=A[m*lda+k]   TA==1: A(m,k)=A[k*lda+m]
//   TB==0: B(k,n)=B[k*ldb+n]   TB==1: B(k,n)=B[n*ldb+k]
// Block 128x128, BK=16, 256 threads (8 warps, 64x32 warp tile),
// mma.sync.m16n8k8 tf32, double-buffered smem with register prefetch.
//
// smem layouts (uint32 tf32 bits), strides chosen for conflict-free
// fragment gathers:
//   TA0: As[m][k] stride 20     TA1: As[k][m] stride 136
//   TB0: Bs[k][n] stride 136    TB1: Bs[n][k] stride 20
// ---------------------------------------------------------------------------
#define BM 128
#define BN 128
#define BK 16

#define MMA_TF32(d, a, b)                                                     \
    asm volatile(                                                             \
        "mma.sync.aligned.m16n8k8.row.col.f32.tf32.tf32.f32 "                 \
        "{%0,%1,%2,%3},{%4,%5,%6,%7},{%8,%9},{%0,%1,%2,%3};"                  \
        : "+f"(d[0]), "+f"(d[1]), "+f"(d[2]), "+f"(d[3])                      \
        : "r"(a[0]), "r"(a[1]), "r"(a[2]), "r"(a[3]), "r"(b[0]), "r"(b[1]))

template<int TA, int TB, bool BIAS, bool RES>
__global__ __launch_bounds__(256) void tgemm_kernel(
    const float* __restrict__ A, int lda, size_t sA,
    const float* __restrict__ B, int ldb, size_t sB,
    float* __restrict__ C, int ldc, size_t sC,
    const float* __restrict__ bias,
    const float* __restrict__ resid, size_t sR,
    int K, float alpha)
{
    __shared__ uint32_t As[2][2560];
    __shared__ uint32_t Bs[2][2560];

    int bz = blockIdx.z;
    A += (size_t)bz * sA;
    B += (size_t)bz * sB;
    C += (size_t)bz * sC;
    if (RES) resid += (size_t)bz * sR;

    const int m0 = blockIdx.y * BM;
    const int n0 = blockIdx.x * BN;
    const int tid = threadIdx.x;
    const int lane = tid & 31;
    const int warp = tid >> 5;
    const int wm = warp >> 2;   // 0..1 : 64-row slab
    const int wn = warp & 3;    // 0..3 : 32-col slab

    // ---- per-thread staging offsets ----
    size_t gA[2]; int soA[2];
    size_t gB[2]; int soB[2];
    #pragma unroll
    for (int t = 0; t < 2; t++) {
        int f = tid * 2 + t;          // 0..511 float4s per tile
        if (TA == 0) {                // tile 128x16, k contiguous
            int m = f >> 2, k4 = (f & 3) << 2;
            gA[t] = (size_t)(m0 + m) * lda + k4;
            soA[t] = m * 20 + k4;
        } else {                      // tile 16x128, m contiguous
            int k = f >> 5, m4 = (f & 31) << 2;
            gA[t] = (size_t)k * lda + m0 + m4;
            soA[t] = k * 136 + m4;
        }
        if (TB == 0) {                // tile 16x128, n contiguous
            int k = f >> 5, n4 = (f & 31) << 2;
            gB[t] = (size_t)k * ldb + n0 + n4;
            soB[t] = k * 136 + n4;
        } else {                      // tile 128x16, k contiguous
            int n = f >> 2, k4 = (f & 3) << 2;
            gB[t] = (size_t)(n0 + n) * ldb + k4;
            soB[t] = n * 20 + k4;
        }
    }
    const size_t stepA = (TA == 0) ? (size_t)BK : (size_t)BK * lda;
    const size_t stepB = (TB == 0) ? (size_t)BK * ldb : (size_t)BK;

    float acc[4][4][4];
    #pragma unroll
    for (int i = 0; i < 4; i++)
        #pragma unroll
        for (int j = 0; j < 4; j++)
            #pragma unroll
            for (int r = 0; r < 4; r++) acc[i][j][r] = 0.f;

    float4 pA[2], pB[2];

    // ---- prologue: stage k-tile 0 ----
    #pragma unroll
    for (int t = 0; t < 2; t++) {
        pA[t] = *(const float4*)(A + gA[t]);
        pB[t] = *(const float4*)(B + gB[t]);
    }
    #pragma unroll
    for (int t = 0; t < 2; t++) {
        uint32_t* dA = &As[0][soA[t]];
        dA[0] = f2tf(pA[t].x); dA[1] = f2tf(pA[t].y);
        dA[2] = f2tf(pA[t].z); dA[3] = f2tf(pA[t].w);
        uint32_t* dB = &Bs[0][soB[t]];
        dB[0] = f2tf(pB[t].x); dB[1] = f2tf(pB[t].y);
        dB[2] = f2tf(pB[t].z); dB[3] = f2tf(pB[t].w);
    }
    __syncthreads();

    const int KT = K / BK;
    for (int kt = 0; kt < KT; kt++) {
        const int cur = kt & 1;
        if (kt + 1 < KT) {
            size_t ko = (size_t)(kt + 1);
            #pragma unroll
            for (int t = 0; t < 2; t++) {
                pA[t] = *(const float4*)(A + gA[t] + ko * stepA);
                pB[t] = *(const float4*)(B + gB[t] + ko * stepB);
            }
        }

        // ---- compute on buffer `cur` ----
        #pragma unroll
        for (int ks = 0; ks < 2; ks++) {
            const int kc = ks * 8 + (lane & 3);
            uint32_t a[4][4], b[4][2];
            #pragma unroll
            for (int mt = 0; mt < 4; mt++) {
                int r = wm * 64 + mt * 16 + (lane >> 2);
                if (TA == 0) {
                    a[mt][0] = As[cur][r * 20 + kc];
                    a[mt][1] = As[cur][(r + 8) * 20 + kc];
                    a[mt][2] = As[cur][r * 20 + kc + 4];
                    a[mt][3] = As[cur][(r + 8) * 20 + kc + 4];
                } else {
                    a[mt][0] = As[cur][kc * 136 + r];
                    a[mt][1] = As[cur][kc * 136 + r + 8];
                    a[mt][2] = As[cur][(kc + 4) * 136 + r];
                    a[mt][3] = As[cur][(kc + 4) * 136 + r + 8];
                }
            }
            #pragma unroll
            for (int nt = 0; nt < 4; nt++) {
                int cn = wn * 32 + nt * 8 + (lane >> 2);
                if (TB == 0) {
                    b[nt][0] = Bs[cur][kc * 136 + cn];
                    b[nt][1] = Bs[cur][(kc + 4) * 136 + cn];
                } else {
                    b[nt][0] = Bs[cur][cn * 20 + kc];
                    b[nt][1] = Bs[cur][cn * 20 + kc + 4];
                }
            }
            #pragma unroll
            for (int mt = 0; mt < 4; mt++)
                #pragma unroll
                for (int nt = 0; nt < 4; nt++)
                    MMA_TF32(acc[mt][nt], a[mt], b[nt]);
        }

        if (kt + 1 < KT) {
            const int nxt = cur ^ 1;
            #pragma unroll
            for (int t = 0; t < 2; t++) {
                uint32_t* dA = &As[nxt][soA[t]];
                dA[0] = f2tf(pA[t].x); dA[1] = f2tf(pA[t].y);
                dA[2] = f2tf(pA[t].z); dA[3] = f2tf(pA[t].w);
                uint32_t* dB = &Bs[nxt][soB[t]];
                dB[0] = f2tf(pB[t].x); dB[1] = f2tf(pB[t].y);
                dB[2] = f2tf(pB[t].z); dB[3] = f2tf(pB[t].w);
            }
        }
        __syncthreads();
    }

    // ---- epilogue ----
    #pragma unroll
    for (int mt = 0; mt < 4; mt++) {
        int mA = m0 + wm * 64 + mt * 16 + (lane >> 2);
        #pragma unroll
        for (int h = 0; h < 2; h++) {
            int m = mA + h * 8;
            float bi = BIAS ? bias[m] : 0.f;
            #pragma unroll
            for (int nt = 0; nt < 4; nt++) {
                int n = n0 + wn * 32 + nt * 8 + 2 * (lane & 3);
                size_t off = (size_t)m * ldc + n;
                float2 o;
                o.x = acc[mt][nt][h * 2 + 0] * alpha + bi;
                o.y = acc[mt][nt][h * 2 + 1] * alpha + bi;
                if (RES) {
                    float2 rr = *(const float2*)(resid + off);
                    o.x += rr.x; o.y += rr.y;
                }
                *(float2*)(C + off) = o;
            }
        }
    }
}

// ---------------------------------------------------------------------------
// Host launcher
// ---------------------------------------------------------------------------
extern "C" void kernel_launch(void* const* d_in, const int* in_sizes, int n_in,
                              void* d_out, int out_size)
{
    const float* x      = (const float*)d_in[0];
    const float* norm_w = (const float*)d_in[1];
    const float* norm_b = (const float*)d_in[2];
    const float* wq     = (const float*)d_in[3];
    const float* bq     = (const float*)d_in[4];
    const float* wk     = (const float*)d_in[5];
    const float* bk     = (const float*)d_in[6];
    const float* wv     = (const float*)d_in[7];
    const float* bv     = (const float*)d_in[8];
    const float* wo     = (const float*)d_in[9];
    const float* bo     = (const float*)d_in[10];
    float* out = (float*)d_out;

    float *h, *q, *k, *v, *s, *ao;
    cudaGetSymbolAddress((void**)&h,  g_h);
    cudaGetSymbolAddress((void**)&q,  g_q);
    cudaGetSymbolAddress((void**)&k,  g_k);
    cudaGetSymbolAddress((void**)&v,  g_v);
    cudaGetSymbolAddress((void**)&s,  g_s);
    cudaGetSymbolAddress((void**)&ao, g_ao);

    const size_t CN = (size_t)CCH * NPIX;
    const size_t NN = (size_t)NPIX * NPIX;
    const float scale = 1.0f / sqrtf((float)CCH);

    // 1. GroupNorm
    groupnorm_kernel<<<BATCH * NGRP, 256>>>(x, norm_w, norm_b, h);

    // 2. q/k/v projections: W[512,512] @ h[512,4096]
    dim3 gProj(NPIX / BN, CCH / BM, BATCH);
    tgemm_kernel<0, 0, true, false><<<gProj, 256>>>(
        wq, CCH, 0, h, NPIX, CN, q, NPIX, CN, bq, nullptr, 0, CCH, 1.0f);
    tgemm_kernel<0, 0, true, false><<<gProj, 256>>>(
        wk, CCH, 0, h, NPIX, CN, k, NPIX, CN, bk, nullptr, 0, CCH, 1.0f);
    tgemm_kernel<0, 0, true, false><<<gProj, 256>>>(
        wv, CCH, 0, h, NPIX, CN, v, NPIX, CN, bv, nullptr, 0, CCH, 1.0f);

    // 3. scores[i,j] = scale * sum_c q[c,i] k[c,j]  (TN, M=N=4096, K=512)
    dim3 gScore(NPIX / BN, NPIX / BM, BATCH);
    tgemm_kernel<1, 0, false, false><<<gScore, 256>>>(
        q, NPIX, CN, k, NPIX, CN, s, NPIX, NN, nullptr, nullptr, 0, CCH, scale);

    // 4. softmax rows, in place
    softmax_kernel<<<BATCH * NPIX, 256>>>(s);

    // 5. ao[c,i] = sum_j v[c,j] attn[i,j]  (NT, M=512, N=4096, K=4096)
    dim3 gOut(NPIX / BN, CCH / BM, BATCH);
    tgemm_kernel<0, 1, false, false><<<gOut, 256>>>(
        v, NPIX, CN, s, NPIX, NN, ao, NPIX, CN, nullptr, nullptr, 0, NPIX, 1.0f);

    // 6. out = x + wo @ ao + bo
    tgemm_kernel<0, 0, true, true><<<gOut, 256>>>(
        wo, CCH, 0, ao, NPIX, CN, out, NPIX, CN, bo, x, CN, CCH, 1.0f);
}

// round 4
// speedup vs baseline: 4.1119x; 1.7718x over previous
#include <cuda_runtime.h>
#include <math.h>
#include <stdint.h>

// Shape fixed by reference: B=2, C=512, H=W=64 -> N=4096, 32 groups.
#define BATCH 2
#define CCH   512
#define NGRP  32
#define NPIX  4096
#define EPSV  1e-6f

// ---------------------------------------------------------------------------
// Scratch
// ---------------------------------------------------------------------------
__device__ float g_h [BATCH * CCH * NPIX];
__device__ float g_q [BATCH * CCH * NPIX];
__device__ float g_k [BATCH * CCH * NPIX];
__device__ float g_v [BATCH * CCH * NPIX];
__device__ float g_s [(size_t)BATCH * NPIX * NPIX];
__device__ float g_ao[BATCH * CCH * NPIX];

// ---------------------------------------------------------------------------
// Helpers
// ---------------------------------------------------------------------------
__device__ __forceinline__ float warpSum(float v) {
    #pragma unroll
    for (int o = 16; o; o >>= 1) v += __shfl_xor_sync(0xffffffffu, v, o);
    return v;
}
__device__ __forceinline__ float warpMax(float v) {
    #pragma unroll
    for (int o = 16; o; o >>= 1) v = fmaxf(v, __shfl_xor_sync(0xffffffffu, v, o));
    return v;
}
// pack two f32 -> bf16x2 (lo = first arg)
__device__ __forceinline__ uint32_t pack_bf16(float lo, float hi) {
    uint32_t u;
    asm("cvt.rn.bf16x2.f32 %0, %1, %2;" : "=r"(u) : "f"(hi), "f"(lo));
    return u;
}
__device__ __forceinline__ void ldsm4(uint32_t& r0, uint32_t& r1,
                                      uint32_t& r2, uint32_t& r3, uint32_t addr) {
    asm volatile("ldmatrix.sync.aligned.x4.m8n8.shared.b16 {%0,%1,%2,%3},[%4];"
                 : "=r"(r0), "=r"(r1), "=r"(r2), "=r"(r3) : "r"(addr));
}
__device__ __forceinline__ void ldsm4t(uint32_t& r0, uint32_t& r1,
                                       uint32_t& r2, uint32_t& r3, uint32_t addr) {
    asm volatile("ldmatrix.sync.aligned.x4.m8n8.trans.shared.b16 {%0,%1,%2,%3},[%4];"
                 : "=r"(r0), "=r"(r1), "=r"(r2), "=r"(r3) : "r"(addr));
}

// ---------------------------------------------------------------------------
// GroupNorm
// ---------------------------------------------------------------------------
__global__ __launch_bounds__(256) void groupnorm_kernel(
    const float* __restrict__ x, const float* __restrict__ w,
    const float* __restrict__ b, float* __restrict__ out)
{
    const int CPG = CCH / NGRP;
    const int GSZ = CPG * NPIX;
    int bg = blockIdx.x;
    int batch = bg / NGRP, g = bg % NGRP;
    size_t base = (size_t)batch * CCH * NPIX + (size_t)g * CPG * NPIX;
    const float4* x4 = (const float4*)(x + base);
    float4* o4 = (float4*)(out + base);
    int tid = threadIdx.x;

    float s = 0.f, ss = 0.f;
    for (int i = tid; i < GSZ / 4; i += 256) {
        float4 v = x4[i];
        s  += v.x + v.y + v.z + v.w;
        ss += v.x * v.x + v.y * v.y + v.z * v.z + v.w * v.w;
    }
    __shared__ float rs[8], rss[8];
    float ws = warpSum(s), wss = warpSum(ss);
    int lane = tid & 31, wid = tid >> 5;
    if (lane == 0) { rs[wid] = ws; rss[wid] = wss; }
    __syncthreads();
    __shared__ float s_mean, s_inv;
    if (tid == 0) {
        float S = 0.f, SS = 0.f;
        #pragma unroll
        for (int i = 0; i < 8; i++) { S += rs[i]; SS += rss[i]; }
        float mean = S / (float)GSZ;
        float var = SS / (float)GSZ - mean * mean;
        s_mean = mean;
        s_inv = rsqrtf(var + EPSV);
    }
    __syncthreads();
    float mean = s_mean, inv = s_inv;

    for (int i = tid; i < GSZ / 4; i += 256) {
        int c = g * CPG + ((i * 4) / NPIX);
        float sc = w[c] * inv;
        float sb = b[c] - mean * sc;
        float4 v = x4[i];
        v.x = v.x * sc + sb; v.y = v.y * sc + sb;
        v.z = v.z * sc + sb; v.w = v.w * sc + sb;
        o4[i] = v;
    }
}

// ---------------------------------------------------------------------------
// Row softmax over 4096 cols, in place.
// ---------------------------------------------------------------------------
__global__ __launch_bounds__(256) void softmax_kernel(float* __restrict__ s)
{
    size_t row = blockIdx.x;
    float4* p = (float4*)(s + row * NPIX);
    int tid = threadIdx.x;
    float4 r[4];
    float m = -1e30f;
    #pragma unroll
    for (int i = 0; i < 4; i++) {
        r[i] = p[tid + i * 256];
        m = fmaxf(m, fmaxf(fmaxf(r[i].x, r[i].y), fmaxf(r[i].z, r[i].w)));
    }
    __shared__ float red[8];
    float wm = warpMax(m);
    int lane = tid & 31, wid = tid >> 5;
    if (lane == 0) red[wid] = wm;
    __syncthreads();
    __shared__ float s_m, s_inv;
    if (tid == 0) {
        float mm = red[0];
        #pragma unroll
        for (int i = 1; i < 8; i++) mm = fmaxf(mm, red[i]);
        s_m = mm;
    }
    __syncthreads();
    m = s_m;
    float sum = 0.f;
    #pragma unroll
    for (int i = 0; i < 4; i++) {
        r[i].x = expf(r[i].x - m); r[i].y = expf(r[i].y - m);
        r[i].z = expf(r[i].z - m); r[i].w = expf(r[i].w - m);
        sum += r[i].x + r[i].y + r[i].z + r[i].w;
    }
    float wsum = warpSum(sum);
    if (lane == 0) red[wid] = wsum;
    __syncthreads();
    if (tid == 0) {
        float S = 0.f;
        #pragma unroll
        for (int i = 0; i < 8; i++) S += red[i];
        s_inv = 1.f / S;
    }
    __syncthreads();
    float inv = s_inv;
    #pragma unroll
    for (int i = 0; i < 4; i++) {
        r[i].x *= inv; r[i].y *= inv; r[i].z *= inv; r[i].w *= inv;
        p[tid + i * 256] = r[i];
    }
}

// ---------------------------------------------------------------------------
// BF16 tensor-core GEMM (mma.m16n8k16 + ldmatrix):
//   C[m,n] = alpha * sum_k A(m,k)*B(k,n)  (+bias[m]) (+resid)
//   TA==0: A(m,k)=A[m*lda+k]   TA==1: A(m,k)=A[k*lda+m]
//   TB==0: B(k,n)=B[k*ldb+n]   TB==1: B(k,n)=B[n*ldb+k]
// Block 128x128, BK=32, 256 threads (8 warps, warp tile 64x32).
// smem (halves): k-contiguous tiles [128][BK] stride 40; m/n-contiguous
// tiles [BK][128] stride 136. Both strides conflict-free for LDSM.
// Fragments: A via ldmatrix(.trans if TA1), B via ldmatrix(.trans if TB0).
// ---------------------------------------------------------------------------
#define BM 128
#define BN 128
#define BK 32

#define MMA_BF16(d, a, b)                                                     \
    asm volatile(                                                             \
        "mma.sync.aligned.m16n8k16.row.col.f32.bf16.bf16.f32 "                \
        "{%0,%1,%2,%3},{%4,%5,%6,%7},{%8,%9},{%0,%1,%2,%3};"                  \
        : "+f"(d[0]), "+f"(d[1]), "+f"(d[2]), "+f"(d[3])                      \
        : "r"(a[0]), "r"(a[1]), "r"(a[2]), "r"(a[3]), "r"(b[0]), "r"(b[1]))

template<int TA, int TB, bool BIAS, bool RES>
__global__ __launch_bounds__(256) void bgemm_kernel(
    const float* __restrict__ A, int lda, size_t sA,
    const float* __restrict__ B, int ldb, size_t sB,
    float* __restrict__ C, int ldc, size_t sC,
    const float* __restrict__ bias,
    const float* __restrict__ resid, size_t sR,
    int K, float alpha)
{
    __shared__ __align__(16) uint16_t As[2][5120];
    __shared__ __align__(16) uint16_t Bs[2][5120];

    int bz = blockIdx.z;
    A += (size_t)bz * sA;
    B += (size_t)bz * sB;
    C += (size_t)bz * sC;
    if (RES) resid += (size_t)bz * sR;

    const int m0 = blockIdx.y * BM;
    const int n0 = blockIdx.x * BN;
    const int tid = threadIdx.x;
    const int lane = tid & 31;
    const int warp = tid >> 5;
    const int wm = warp >> 2;          // 0..1
    const int wn = warp & 3;           // 0..3
    const int R  = wm * 64;            // warp row base in tile
    const int CN = wn * 32;            // warp col base in tile

    const uint32_t asm0 = (uint32_t)__cvta_generic_to_shared(&As[0][0]);
    const uint32_t asm1 = (uint32_t)__cvta_generic_to_shared(&As[1][0]);
    const uint32_t bsm0 = (uint32_t)__cvta_generic_to_shared(&Bs[0][0]);
    const uint32_t bsm1 = (uint32_t)__cvta_generic_to_shared(&Bs[1][0]);

    // ---- staging offsets: 4 float4 chunks per operand per thread ----
    size_t gA[4]; int soA[4];
    size_t gB[4]; int soB[4];
    #pragma unroll
    for (int t = 0; t < 4; t++) {
        int f = tid + t * 256;           // 0..1023 float4s (tile = 4096 elems)
        if (TA == 0) {                   // [128][32] k-contig, stride 40
            int m = f >> 3, k4 = (f & 7) << 2;
            gA[t] = (size_t)(m0 + m) * lda + k4;
            soA[t] = m * 40 + k4;
        } else {                         // [32][128] m-contig, stride 136
            int k = f >> 5, m4 = (f & 31) << 2;
            gA[t] = (size_t)k * lda + m0 + m4;
            soA[t] = k * 136 + m4;
        }
        if (TB == 0) {                   // [32][128] n-contig, stride 136
            int k = f >> 5, n4 = (f & 31) << 2;
            gB[t] = (size_t)k * ldb + n0 + n4;
            soB[t] = k * 136 + n4;
        } else {                         // [128][32] k-contig, stride 40
            int n = f >> 3, k4 = (f & 7) << 2;
            gB[t] = (size_t)(n0 + n) * ldb + k4;
            soB[t] = n * 40 + k4;
        }
    }
    const size_t stepA = (TA == 0) ? (size_t)BK : (size_t)BK * lda;
    const size_t stepB = (TB == 0) ? (size_t)BK * ldb : (size_t)BK;

    // ---- lane-derived fragment base offsets (halves) ----
    const int lq = lane & 7;
    const int b1 = (lane >> 3) & 1;
    const int b2 = lane >> 4;
    int aBase, bBase;
    if (TA == 0) aBase = (R + lq + 8 * b1) * 40 + 8 * b2;
    else         aBase = (lq + 8 * b2) * 136 + R + 8 * b1;
    if (TB == 0) bBase = (lq + 8 * b1) * 136 + CN + 8 * b2;
    else         bBase = (CN + lq + 8 * b2) * 40 + 8 * b1;

    float acc[4][4][4];
    #pragma unroll
    for (int i = 0; i < 4; i++)
        #pragma unroll
        for (int j = 0; j < 4; j++)
            #pragma unroll
            for (int r = 0; r < 4; r++) acc[i][j][r] = 0.f;

    float4 pA[4], pB[4];

    // ---- prologue: stage k-tile 0 ----
    #pragma unroll
    for (int t = 0; t < 4; t++) {
        pA[t] = *(const float4*)(A + gA[t]);
        pB[t] = *(const float4*)(B + gB[t]);
    }
    #pragma unroll
    for (int t = 0; t < 4; t++) {
        uint2 ua = make_uint2(pack_bf16(pA[t].x, pA[t].y), pack_bf16(pA[t].z, pA[t].w));
        *(uint2*)&As[0][soA[t]] = ua;
        uint2 ub = make_uint2(pack_bf16(pB[t].x, pB[t].y), pack_bf16(pB[t].z, pB[t].w));
        *(uint2*)&Bs[0][soB[t]] = ub;
    }
    __syncthreads();

    const int KT = K / BK;
    for (int kt = 0; kt < KT; kt++) {
        const int cur = kt & 1;
        const uint32_t aSm = cur ? asm1 : asm0;
        const uint32_t bSm = cur ? bsm1 : bsm0;

        if (kt + 1 < KT) {
            size_t ko = (size_t)(kt + 1);
            #pragma unroll
            for (int t = 0; t < 4; t++) {
                pA[t] = *(const float4*)(A + gA[t] + ko * stepA);
                pB[t] = *(const float4*)(B + gB[t] + ko * stepB);
            }
        }

        #pragma unroll
        for (int ks = 0; ks < 2; ks++) {
            uint32_t a[4][4], b[4][2];
            #pragma unroll
            for (int mt = 0; mt < 4; mt++) {
                int off = (TA == 0) ? (aBase + mt * 640 + ks * 16)
                                    : (aBase + ks * 2176 + mt * 16);
                uint32_t addr = aSm + 2 * off;
                if (TA == 0) ldsm4 (a[mt][0], a[mt][1], a[mt][2], a[mt][3], addr);
                else         ldsm4t(a[mt][0], a[mt][1], a[mt][2], a[mt][3], addr);
            }
            #pragma unroll
            for (int ntp = 0; ntp < 2; ntp++) {
                int off = (TB == 0) ? (bBase + ks * 2176 + ntp * 16)
                                    : (bBase + ntp * 640 + ks * 16);
                uint32_t addr = bSm + 2 * off;
                if (TB == 0)
                    ldsm4t(b[ntp*2][0], b[ntp*2][1], b[ntp*2+1][0], b[ntp*2+1][1], addr);
                else
                    ldsm4 (b[ntp*2][0], b[ntp*2][1], b[ntp*2+1][0], b[ntp*2+1][1], addr);
            }
            #pragma unroll
            for (int mt = 0; mt < 4; mt++)
                #pragma unroll
                for (int nt = 0; nt < 4; nt++)
                    MMA_BF16(acc[mt][nt], a[mt], b[nt]);
        }

        if (kt + 1 < KT) {
            const int nxt = cur ^ 1;
            #pragma unroll
            for (int t = 0; t < 4; t++) {
                uint2 ua = make_uint2(pack_bf16(pA[t].x, pA[t].y), pack_bf16(pA[t].z, pA[t].w));
                *(uint2*)&As[nxt][soA[t]] = ua;
                uint2 ub = make_uint2(pack_bf16(pB[t].x, pB[t].y), pack_bf16(pB[t].z, pB[t].w));
                *(uint2*)&Bs[nxt][soB[t]] = ub;
            }
        }
        __syncthreads();
    }

    // ---- epilogue ----
    #pragma unroll
    for (int mt = 0; mt < 4; mt++) {
        int mA = m0 + R + mt * 16 + (lane >> 2);
        #pragma unroll
        for (int h = 0; h < 2; h++) {
            int m = mA + h * 8;
            float bi = BIAS ? bias[m] : 0.f;
            #pragma unroll
            for (int nt = 0; nt < 4; nt++) {
                int n = n0 + CN + nt * 8 + 2 * (lane & 3);
                size_t off = (size_t)m * ldc + n;
                float2 o;
                o.x = acc[mt][nt][h * 2 + 0] * alpha + bi;
                o.y = acc[mt][nt][h * 2 + 1] * alpha + bi;
                if (RES) {
                    float2 rr = *(const float2*)(resid + off);
                    o.x += rr.x; o.y += rr.y;
                }
                *(float2*)(C + off) = o;
            }
        }
    }
}

// ---------------------------------------------------------------------------
// Host launcher
// ---------------------------------------------------------------------------
extern "C" void kernel_launch(void* const* d_in, const int* in_sizes, int n_in,
                              void* d_out, int out_size)
{
    const float* x      = (const float*)d_in[0];
    const float* norm_w = (const float*)d_in[1];
    const float* norm_b = (const float*)d_in[2];
    const float* wq     = (const float*)d_in[3];
    const float* bq     = (const float*)d_in[4];
    const float* wk     = (const float*)d_in[5];
    const float* bk     = (const float*)d_in[6];
    const float* wv     = (const float*)d_in[7];
    const float* bv     = (const float*)d_in[8];
    const float* wo     = (const float*)d_in[9];
    const float* bo     = (const float*)d_in[10];
    float* out = (float*)d_out;

    float *h, *q, *k, *v, *s, *ao;
    cudaGetSymbolAddress((void**)&h,  g_h);
    cudaGetSymbolAddress((void**)&q,  g_q);
    cudaGetSymbolAddress((void**)&k,  g_k);
    cudaGetSymbolAddress((void**)&v,  g_v);
    cudaGetSymbolAddress((void**)&s,  g_s);
    cudaGetSymbolAddress((void**)&ao, g_ao);

    const size_t CN = (size_t)CCH * NPIX;
    const size_t NN = (size_t)NPIX * NPIX;
    const float scale = 1.0f / sqrtf((float)CCH);

    // 1. GroupNorm
    groupnorm_kernel<<<BATCH * NGRP, 256>>>(x, norm_w, norm_b, h);

    // 2. q/k/v projections: W[512,512] @ h[512,4096]
    dim3 gProj(NPIX / BN, CCH / BM, BATCH);
    bgemm_kernel<0, 0, true, false><<<gProj, 256>>>(
        wq, CCH, 0, h, NPIX, CN, q, NPIX, CN, bq, nullptr, 0, CCH, 1.0f);
    bgemm_kernel<0, 0, true, false><<<gProj, 256>>>(
        wk, CCH, 0, h, NPIX, CN, k, NPIX, CN, bk, nullptr, 0, CCH, 1.0f);
    bgemm_kernel<0, 0, true, false><<<gProj, 256>>>(
        wv, CCH, 0, h, NPIX, CN, v, NPIX, CN, bv, nullptr, 0, CCH, 1.0f);

    // 3. scores[i,j] = scale * sum_c q[c,i] k[c,j]  (TA1/TB0, M=N=4096, K=512)
    dim3 gScore(NPIX / BN, NPIX / BM, BATCH);
    bgemm_kernel<1, 0, false, false><<<gScore, 256>>>(
        q, NPIX, CN, k, NPIX, CN, s, NPIX, NN, nullptr, nullptr, 0, CCH, scale);

    // 4. softmax rows, in place
    softmax_kernel<<<BATCH * NPIX, 256>>>(s);

    // 5. ao[c,i] = sum_j v[c,j] attn[i,j]  (TA0/TB1, M=512, N=4096, K=4096)
    dim3 gOut(NPIX / BN, CCH / BM, BATCH);
    bgemm_kernel<0, 1, false, false><<<gOut, 256>>>(
        v, NPIX, CN, s, NPIX, NN, ao, NPIX, CN, nullptr, nullptr, 0, NPIX, 1.0f);

    // 6. out = x + wo @ ao + bo
    bgemm_kernel<0, 0, true, true><<<gOut, 256>>>(
        wo, CCH, 0, ao, NPIX, CN, out, NPIX, CN, bo, x, CN, CCH, 1.0f);
}

// round 5
// speedup vs baseline: 5.1760x; 1.2588x over previous
#include <cuda_runtime.h>
#include <cuda_bf16.h>
#include <math.h>
#include <stdint.h>

// Shape fixed by reference: B=2, C=512, H=W=64 -> N=4096, 32 groups.
#define BATCH 2
#define CCH   512
#define NGRP  32
#define NPIX  4096
#define EPSV  1e-6f

// ---------------------------------------------------------------------------
// Scratch (bf16 intermediates; fp32 scores only)
// ---------------------------------------------------------------------------
__device__ __nv_bfloat16 g_wb[4][CCH * CCH];          // wq,wk,wv,wo in bf16
__device__ __nv_bfloat16 g_hb [BATCH * CCH * NPIX];   // groupnorm out
__device__ __nv_bfloat16 g_qb [BATCH * CCH * NPIX];
__device__ __nv_bfloat16 g_kb [BATCH * CCH * NPIX];
__device__ __nv_bfloat16 g_vb [BATCH * CCH * NPIX];
__device__ __nv_bfloat16 g_ab [(size_t)BATCH * NPIX * NPIX]; // attn (bf16)
__device__ __nv_bfloat16 g_aob[BATCH * CCH * NPIX];   // attention output
__device__ float         g_s  [(size_t)BATCH * NPIX * NPIX]; // scores fp32

// ---------------------------------------------------------------------------
// Helpers
// ---------------------------------------------------------------------------
__device__ __forceinline__ float warpSum(float v) {
    #pragma unroll
    for (int o = 16; o; o >>= 1) v += __shfl_xor_sync(0xffffffffu, v, o);
    return v;
}
__device__ __forceinline__ float warpMax(float v) {
    #pragma unroll
    for (int o = 16; o; o >>= 1) v = fmaxf(v, __shfl_xor_sync(0xffffffffu, v, o));
    return v;
}
// pack two f32 -> bf16x2 (lo = first arg)
__device__ __forceinline__ uint32_t pack_bf16(float lo, float hi) {
    uint32_t u;
    asm("cvt.rn.bf16x2.f32 %0, %1, %2;" : "=r"(u) : "f"(hi), "f"(lo));
    return u;
}
__device__ __forceinline__ void ldsm4(uint32_t& r0, uint32_t& r1,
                                      uint32_t& r2, uint32_t& r3, uint32_t addr) {
    asm volatile("ldmatrix.sync.aligned.x4.m8n8.shared.b16 {%0,%1,%2,%3},[%4];"
                 : "=r"(r0), "=r"(r1), "=r"(r2), "=r"(r3) : "r"(addr));
}
__device__ __forceinline__ void ldsm4t(uint32_t& r0, uint32_t& r1,
                                       uint32_t& r2, uint32_t& r3, uint32_t addr) {
    asm volatile("ldmatrix.sync.aligned.x4.m8n8.trans.shared.b16 {%0,%1,%2,%3},[%4];"
                 : "=r"(r0), "=r"(r1), "=r"(r2), "=r"(r3) : "r"(addr));
}
__device__ __forceinline__ void cpasync16(uint32_t smem, const void* g) {
    asm volatile("cp.async.cg.shared.global [%0],[%1],16;" :: "r"(smem), "l"(g));
}
#define CP_COMMIT() asm volatile("cp.async.commit_group;")
#define CP_WAIT1()  asm volatile("cp.async.wait_group 1;")

// ---------------------------------------------------------------------------
// Weight fp32 -> bf16 conversion (one matrix per launch, 512x512)
// ---------------------------------------------------------------------------
__global__ __launch_bounds__(256) void cvtw_kernel(
    const float* __restrict__ s, __nv_bfloat16* __restrict__ d)
{
    int i = blockIdx.x * 256 + threadIdx.x;           // float4 index
    float4 v = ((const float4*)s)[i];
    ((uint2*)d)[i] = make_uint2(pack_bf16(v.x, v.y), pack_bf16(v.z, v.w));
}

// ---------------------------------------------------------------------------
// GroupNorm: fp32 in -> bf16 out
// ---------------------------------------------------------------------------
__global__ __launch_bounds__(256) void groupnorm_kernel(
    const float* __restrict__ x, const float* __restrict__ w,
    const float* __restrict__ b, __nv_bfloat16* __restrict__ out)
{
    const int CPG = CCH / NGRP;
    const int GSZ = CPG * NPIX;
    int bg = blockIdx.x;
    int batch = bg / NGRP, g = bg % NGRP;
    size_t base = (size_t)batch * CCH * NPIX + (size_t)g * CPG * NPIX;
    const float4* x4 = (const float4*)(x + base);
    uint2* o2 = (uint2*)(out + base);
    int tid = threadIdx.x;

    float s = 0.f, ss = 0.f;
    for (int i = tid; i < GSZ / 4; i += 256) {
        float4 v = x4[i];
        s  += v.x + v.y + v.z + v.w;
        ss += v.x * v.x + v.y * v.y + v.z * v.z + v.w * v.w;
    }
    __shared__ float rs[8], rss[8];
    float ws = warpSum(s), wss = warpSum(ss);
    int lane = tid & 31, wid = tid >> 5;
    if (lane == 0) { rs[wid] = ws; rss[wid] = wss; }
    __syncthreads();
    __shared__ float s_mean, s_inv;
    if (tid == 0) {
        float S = 0.f, SS = 0.f;
        #pragma unroll
        for (int i = 0; i < 8; i++) { S += rs[i]; SS += rss[i]; }
        float mean = S / (float)GSZ;
        float var = SS / (float)GSZ - mean * mean;
        s_mean = mean;
        s_inv = rsqrtf(var + EPSV);
    }
    __syncthreads();
    float mean = s_mean, inv = s_inv;

    for (int i = tid; i < GSZ / 4; i += 256) {
        int c = g * CPG + ((i * 4) / NPIX);
        float sc = w[c] * inv;
        float sb = b[c] - mean * sc;
        float4 v = x4[i];
        v.x = v.x * sc + sb; v.y = v.y * sc + sb;
        v.z = v.z * sc + sb; v.w = v.w * sc + sb;
        o2[i] = make_uint2(pack_bf16(v.x, v.y), pack_bf16(v.z, v.w));
    }
}

// ---------------------------------------------------------------------------
// Row softmax: fp32 scores in -> bf16 attn out
// ---------------------------------------------------------------------------
__global__ __launch_bounds__(256) void softmax_kernel(
    const float* __restrict__ s, __nv_bfloat16* __restrict__ a)
{
    size_t row = blockIdx.x;
    const float4* p = (const float4*)(s + row * NPIX);
    uint2* o2 = (uint2*)(a + row * NPIX);
    int tid = threadIdx.x;
    float4 r[4];
    float m = -1e30f;
    #pragma unroll
    for (int i = 0; i < 4; i++) {
        r[i] = p[tid + i * 256];
        m = fmaxf(m, fmaxf(fmaxf(r[i].x, r[i].y), fmaxf(r[i].z, r[i].w)));
    }
    __shared__ float red[8];
    float wm = warpMax(m);
    int lane = tid & 31, wid = tid >> 5;
    if (lane == 0) red[wid] = wm;
    __syncthreads();
    __shared__ float s_m, s_inv;
    if (tid == 0) {
        float mm = red[0];
        #pragma unroll
        for (int i = 1; i < 8; i++) mm = fmaxf(mm, red[i]);
        s_m = mm;
    }
    __syncthreads();
    m = s_m;
    float sum = 0.f;
    #pragma unroll
    for (int i = 0; i < 4; i++) {
        r[i].x = expf(r[i].x - m); r[i].y = expf(r[i].y - m);
        r[i].z = expf(r[i].z - m); r[i].w = expf(r[i].w - m);
        sum += r[i].x + r[i].y + r[i].z + r[i].w;
    }
    float wsum = warpSum(sum);
    if (lane == 0) red[wid] = wsum;
    __syncthreads();
    if (tid == 0) {
        float S = 0.f;
        #pragma unroll
        for (int i = 0; i < 8; i++) S += red[i];
        s_inv = 1.f / S;
    }
    __syncthreads();
    float inv = s_inv;
    #pragma unroll
    for (int i = 0; i < 4; i++) {
        o2[tid + i * 256] = make_uint2(pack_bf16(r[i].x * inv, r[i].y * inv),
                                       pack_bf16(r[i].z * inv, r[i].w * inv));
    }
}

// ---------------------------------------------------------------------------
// BF16 tensor-core GEMM with cp.async double buffer:
//   C[m,n] = alpha * sum_k A(m,k)*B(k,n)  (+bias[m]) (+resid)
//   TA==0: A(m,k)=A[m*lda+k]   TA==1: A(m,k)=A[k*lda+m]
//   TB==0: B(k,n)=B[k*ldb+n]   TB==1: B(k,n)=B[n*ldb+k]
//   OBF: output bf16 (else fp32)
// Block 128x128, BK=32, 256 threads (8 warps, warp tile 64x32).
// smem (halves): k-contig tiles [128][32] stride 40; m/n-contig [32][128]
// stride 136; both conflict-free for LDSM (validated in R4).
// ---------------------------------------------------------------------------
#define BM 128
#define BN 128
#define BK 32

#define MMA_BF16(d, a, b)                                                     \
    asm volatile(                                                             \
        "mma.sync.aligned.m16n8k16.row.col.f32.bf16.bf16.f32 "                \
        "{%0,%1,%2,%3},{%4,%5,%6,%7},{%8,%9},{%0,%1,%2,%3};"                  \
        : "+f"(d[0]), "+f"(d[1]), "+f"(d[2]), "+f"(d[3])                      \
        : "r"(a[0]), "r"(a[1]), "r"(a[2]), "r"(a[3]), "r"(b[0]), "r"(b[1]))

template<int TA, int TB, bool BIAS, bool RES, bool OBF>
__global__ __launch_bounds__(256) void bgemm_kernel(
    const __nv_bfloat16* __restrict__ A, int lda, size_t sA,
    const __nv_bfloat16* __restrict__ B, int ldb, size_t sB,
    void* __restrict__ Cv, int ldc, size_t sC,
    const float* __restrict__ bias,
    const float* __restrict__ resid, size_t sR,
    int K, float alpha)
{
    __shared__ __align__(16) uint16_t As[2][5120];
    __shared__ __align__(16) uint16_t Bs[2][5120];

    int bz = blockIdx.z;
    A += (size_t)bz * sA;
    B += (size_t)bz * sB;
    if (RES) resid += (size_t)bz * sR;

    const int m0 = blockIdx.y * BM;
    const int n0 = blockIdx.x * BN;
    const int tid = threadIdx.x;
    const int lane = tid & 31;
    const int warp = tid >> 5;
    const int wm = warp >> 2;          // 0..1
    const int wn = warp & 3;           // 0..3
    const int R  = wm * 64;
    const int CN = wn * 32;

    uint32_t aSm[2], bSm[2];
    aSm[0] = (uint32_t)__cvta_generic_to_shared(&As[0][0]);
    aSm[1] = (uint32_t)__cvta_generic_to_shared(&As[1][0]);
    bSm[0] = (uint32_t)__cvta_generic_to_shared(&Bs[0][0]);
    bSm[1] = (uint32_t)__cvta_generic_to_shared(&Bs[1][0]);

    // ---- staging: 2 x 16B chunks per operand per thread (tile = 8192B) ----
    size_t gA[2]; int soA[2];
    size_t gB[2]; int soB[2];
    #pragma unroll
    for (int t = 0; t < 2; t++) {
        int f = tid + t * 256;                 // 0..511 chunks
        if (TA == 0) {                         // [128][32] k-contig, stride 40
            int m = f >> 2, c8 = (f & 3) << 3;
            gA[t] = (size_t)(m0 + m) * lda + c8;
            soA[t] = m * 40 + c8;
        } else {                               // [32][128] m-contig, stride 136
            int k = f >> 4, c8 = (f & 15) << 3;
            gA[t] = (size_t)k * lda + m0 + c8;
            soA[t] = k * 136 + c8;
        }
        if (TB == 0) {                         // [32][128] n-contig, stride 136
            int k = f >> 4, c8 = (f & 15) << 3;
            gB[t] = (size_t)k * ldb + n0 + c8;
            soB[t] = k * 136 + c8;
        } else {                               // [128][32] k-contig, stride 40
            int n = f >> 2, c8 = (f & 3) << 3;
            gB[t] = (size_t)(n0 + n) * ldb + c8;
            soB[t] = n * 40 + c8;
        }
    }
    const size_t stepA = (TA == 0) ? (size_t)BK : (size_t)BK * lda;
    const size_t stepB = (TB == 0) ? (size_t)BK * ldb : (size_t)BK;

    // ---- lane-derived LDSM base offsets (halves) ----
    const int lq = lane & 7;
    const int b1 = (lane >> 3) & 1;
    const int b2 = lane >> 4;
    int aBase, bBase;
    if (TA == 0) aBase = (R + lq + 8 * b1) * 40 + 8 * b2;
    else         aBase = (lq + 8 * b2) * 136 + R + 8 * b1;
    if (TB == 0) bBase = (lq + 8 * b1) * 136 + CN + 8 * b2;
    else         bBase = (CN + lq + 8 * b2) * 40 + 8 * b1;

    float acc[4][4][4];
    #pragma unroll
    for (int i = 0; i < 4; i++)
        #pragma unroll
        for (int j = 0; j < 4; j++)
            #pragma unroll
            for (int r = 0; r < 4; r++) acc[i][j][r] = 0.f;

    const int KT = K / BK;

    // ---- prologue: async-stage tiles 0 and 1 ----
    #pragma unroll
    for (int s = 0; s < 2; s++) {
        #pragma unroll
        for (int t = 0; t < 2; t++) {
            cpasync16(aSm[s] + 2 * soA[t], A + gA[t] + (size_t)s * stepA);
            cpasync16(bSm[s] + 2 * soB[t], B + gB[t] + (size_t)s * stepB);
        }
        CP_COMMIT();
    }

    for (int kt = 0; kt < KT; kt++) {
        const int cur = kt & 1;
        CP_WAIT1();
        __syncthreads();

        const uint32_t aS = aSm[cur], bS = bSm[cur];
        #pragma unroll
        for (int ks = 0; ks < 2; ks++) {
            uint32_t a[4][4], b[4][2];
            #pragma unroll
            for (int mt = 0; mt < 4; mt++) {
                int off = (TA == 0) ? (aBase + mt * 640 + ks * 16)
                                    : (aBase + ks * 2176 + mt * 16);
                uint32_t addr = aS + 2 * off;
                if (TA == 0) ldsm4 (a[mt][0], a[mt][1], a[mt][2], a[mt][3], addr);
                else         ldsm4t(a[mt][0], a[mt][1], a[mt][2], a[mt][3], addr);
            }
            #pragma unroll
            for (int ntp = 0; ntp < 2; ntp++) {
                int off = (TB == 0) ? (bBase + ks * 2176 + ntp * 16)
                                    : (bBase + ntp * 640 + ks * 16);
                uint32_t addr = bS + 2 * off;
                if (TB == 0)
                    ldsm4t(b[ntp*2][0], b[ntp*2][1], b[ntp*2+1][0], b[ntp*2+1][1], addr);
                else
                    ldsm4 (b[ntp*2][0], b[ntp*2][1], b[ntp*2+1][0], b[ntp*2+1][1], addr);
            }
            #pragma unroll
            for (int mt = 0; mt < 4; mt++)
                #pragma unroll
                for (int nt = 0; nt < 4; nt++)
                    MMA_BF16(acc[mt][nt], a[mt], b[nt]);
        }

        __syncthreads();
        if (kt + 2 < KT) {
            size_t ko = (size_t)(kt + 2);
            #pragma unroll
            for (int t = 0; t < 2; t++) {
                cpasync16(aSm[cur] + 2 * soA[t], A + gA[t] + ko * stepA);
                cpasync16(bSm[cur] + 2 * soB[t], B + gB[t] + ko * stepB);
            }
            CP_COMMIT();
        }
    }

    // ---- epilogue ----
    #pragma unroll
    for (int mt = 0; mt < 4; mt++) {
        int mA = m0 + R + mt * 16 + (lane >> 2);
        #pragma unroll
        for (int h = 0; h < 2; h++) {
            int m = mA + h * 8;
            float bi = BIAS ? bias[m] : 0.f;
            #pragma unroll
            for (int nt = 0; nt < 4; nt++) {
                int n = n0 + CN + nt * 8 + 2 * (lane & 3);
                size_t off = (size_t)m * ldc + n;
                float ox = acc[mt][nt][h * 2 + 0] * alpha + bi;
                float oy = acc[mt][nt][h * 2 + 1] * alpha + bi;
                if (OBF) {
                    __nv_bfloat16* Cb = (__nv_bfloat16*)Cv + (size_t)bz * sC;
                    *(uint32_t*)(Cb + off) = pack_bf16(ox, oy);
                } else {
                    float* Cf = (float*)Cv + (size_t)bz * sC;
                    if (RES) {
                        float2 rr = *(const float2*)(resid + off);
                        ox += rr.x; oy += rr.y;
                    }
                    float2 o2 = make_float2(ox, oy);
                    *(float2*)(Cf + off) = o2;
                }
            }
        }
    }
}

// ---------------------------------------------------------------------------
// Host launcher
// ---------------------------------------------------------------------------
extern "C" void kernel_launch(void* const* d_in, const int* in_sizes, int n_in,
                              void* d_out, int out_size)
{
    const float* x      = (const float*)d_in[0];
    const float* norm_w = (const float*)d_in[1];
    const float* norm_b = (const float*)d_in[2];
    const float* wq     = (const float*)d_in[3];
    const float* bq     = (const float*)d_in[4];
    const float* wk     = (const float*)d_in[5];
    const float* bk     = (const float*)d_in[6];
    const float* wv     = (const float*)d_in[7];
    const float* bv     = (const float*)d_in[8];
    const float* wo     = (const float*)d_in[9];
    const float* bo     = (const float*)d_in[10];
    float* out = (float*)d_out;

    __nv_bfloat16 *wb, *hb, *qb, *kb, *vb, *ab, *aob;
    float* s;
    cudaGetSymbolAddress((void**)&wb,  g_wb);
    cudaGetSymbolAddress((void**)&hb,  g_hb);
    cudaGetSymbolAddress((void**)&qb,  g_qb);
    cudaGetSymbolAddress((void**)&kb,  g_kb);
    cudaGetSymbolAddress((void**)&vb,  g_vb);
    cudaGetSymbolAddress((void**)&ab,  g_ab);
    cudaGetSymbolAddress((void**)&aob, g_aob);
    cudaGetSymbolAddress((void**)&s,   g_s);
    __nv_bfloat16* wqb = wb;
    __nv_bfloat16* wkb = wb + (size_t)CCH * CCH;
    __nv_bfloat16* wvb = wb + (size_t)2 * CCH * CCH;
    __nv_bfloat16* wob = wb + (size_t)3 * CCH * CCH;

    const size_t CN = (size_t)CCH * NPIX;
    const size_t NN = (size_t)NPIX * NPIX;
    const float scale = 1.0f / sqrtf((float)CCH);
    const int WG = (CCH * CCH / 4) / 256;   // 256 blocks per weight matrix

    // 0. weights -> bf16
    cvtw_kernel<<<WG, 256>>>(wq, wqb);
    cvtw_kernel<<<WG, 256>>>(wk, wkb);
    cvtw_kernel<<<WG, 256>>>(wv, wvb);
    cvtw_kernel<<<WG, 256>>>(wo, wob);

    // 1. GroupNorm -> bf16 h
    groupnorm_kernel<<<BATCH * NGRP, 256>>>(x, norm_w, norm_b, hb);

    // 2. q/k/v projections: W[512,512] @ h[512,4096] -> bf16
    dim3 gProj(NPIX / BN, CCH / BM, BATCH);
    bgemm_kernel<0, 0, true, false, true><<<gProj, 256>>>(
        wqb, CCH, 0, hb, NPIX, CN, qb, NPIX, CN, bq, nullptr, 0, CCH, 1.0f);
    bgemm_kernel<0, 0, true, false, true><<<gProj, 256>>>(
        wkb, CCH, 0, hb, NPIX, CN, kb, NPIX, CN, bk, nullptr, 0, CCH, 1.0f);
    bgemm_kernel<0, 0, true, false, true><<<gProj, 256>>>(
        wvb, CCH, 0, hb, NPIX, CN, vb, NPIX, CN, bv, nullptr, 0, CCH, 1.0f);

    // 3. scores = scale * q^T k  (fp32 out; M=N=4096, K=512)
    dim3 gScore(NPIX / BN, NPIX / BM, BATCH);
    bgemm_kernel<1, 0, false, false, false><<<gScore, 256>>>(
        qb, NPIX, CN, kb, NPIX, CN, s, NPIX, NN, nullptr, nullptr, 0, CCH, scale);

    // 4. softmax rows -> bf16 attn
    softmax_kernel<<<BATCH * NPIX, 256>>>(s, ab);

    // 5. ao[c,i] = sum_j v[c,j] attn[i,j]  (M=512, N=4096, K=4096) -> bf16
    dim3 gOut(NPIX / BN, CCH / BM, BATCH);
    bgemm_kernel<0, 1, false, false, true><<<gOut, 256>>>(
        vb, NPIX, CN, ab, NPIX, NN, aob, NPIX, CN, nullptr, nullptr, 0, NPIX, 1.0f);

    // 6. out = x + wo @ ao + bo  (fp32 out + residual)
    bgemm_kernel<0, 0, true, true, false><<<gOut, 256>>>(
        wob, CCH, 0, aob, NPIX, CN, out, NPIX, CN, bo, x, CN, CCH, 1.0f);
}

// round 7
// speedup vs baseline: 6.2646x; 1.2103x over previous
#include <cuda_runtime.h>
#include <cuda_bf16.h>
#include <math.h>
#include <stdint.h>

// Shape fixed by reference: B=2, C=512, H=W=64 -> N=4096, 32 groups.
#define BATCH 2
#define CCH   512
#define NGRP  32
#define NPIX  4096
#define EPSV  1e-6f

// ---------------------------------------------------------------------------
// Scratch (bf16 intermediates; fp32 scores only)
// ---------------------------------------------------------------------------
__device__ __nv_bfloat16 g_wb[4 * CCH * CCH];         // wq,wk,wv,wo in bf16
__device__ __nv_bfloat16 g_hb [BATCH * CCH * NPIX];   // groupnorm out
__device__ __nv_bfloat16 g_qb [BATCH * CCH * NPIX];
__device__ __nv_bfloat16 g_kb [BATCH * CCH * NPIX];
__device__ __nv_bfloat16 g_vb [BATCH * CCH * NPIX];
__device__ __nv_bfloat16 g_ab [(size_t)BATCH * NPIX * NPIX]; // attn (bf16)
__device__ __nv_bfloat16 g_aob[BATCH * CCH * NPIX];   // attention output
__device__ float         g_s  [(size_t)BATCH * NPIX * NPIX]; // scores fp32

// ---------------------------------------------------------------------------
// Helpers
// ---------------------------------------------------------------------------
__device__ __forceinline__ float warpSum(float v) {
    #pragma unroll
    for (int o = 16; o; o >>= 1) v += __shfl_xor_sync(0xffffffffu, v, o);
    return v;
}
__device__ __forceinline__ float warpMax(float v) {
    #pragma unroll
    for (int o = 16; o; o >>= 1) v = fmaxf(v, __shfl_xor_sync(0xffffffffu, v, o));
    return v;
}
// pack two f32 -> bf16x2 (lo = first arg)
__device__ __forceinline__ uint32_t pack_bf16(float lo, float hi) {
    uint32_t u;
    asm("cvt.rn.bf16x2.f32 %0, %1, %2;" : "=r"(u) : "f"(hi), "f"(lo));
    return u;
}
__device__ __forceinline__ void ldsm4(uint32_t& r0, uint32_t& r1,
                                      uint32_t& r2, uint32_t& r3, uint32_t addr) {
    asm volatile("ldmatrix.sync.aligned.x4.m8n8.shared.b16 {%0,%1,%2,%3},[%4];"
                 : "=r"(r0), "=r"(r1), "=r"(r2), "=r"(r3) : "r"(addr));
}
__device__ __forceinline__ void ldsm4t(uint32_t& r0, uint32_t& r1,
                                       uint32_t& r2, uint32_t& r3, uint32_t addr) {
    asm volatile("ldmatrix.sync.aligned.x4.m8n8.trans.shared.b16 {%0,%1,%2,%3},[%4];"
                 : "=r"(r0), "=r"(r1), "=r"(r2), "=r"(r3) : "r"(addr));
}
__device__ __forceinline__ void cpasync16(uint32_t smem, const void* g) {
    asm volatile("cp.async.cg.shared.global [%0],[%1],16;" :: "r"(smem), "l"(g));
}
#define CP_COMMIT() asm volatile("cp.async.commit_group;")

// ---------------------------------------------------------------------------
// Weights fp32 -> bf16 (all four matrices, one launch)
// ---------------------------------------------------------------------------
__global__ __launch_bounds__(256) void cvtw_kernel(
    const float* __restrict__ wq, const float* __restrict__ wk,
    const float* __restrict__ wv, const float* __restrict__ wo,
    __nv_bfloat16* __restrict__ dst)
{
    int b = blockIdx.x;
    int mi = b >> 7, blk = b & 127;
    const float* src = (mi == 0) ? wq : (mi == 1) ? wk : (mi == 2) ? wv : wo;
    const float4* s4 = (const float4*)src;
    uint2* d2 = (uint2*)(dst + (size_t)mi * CCH * CCH);
    #pragma unroll
    for (int t = 0; t < 2; t++) {
        int i = blk * 512 + threadIdx.x + t * 256;
        float4 v = s4[i];
        d2[i] = make_uint2(pack_bf16(v.x, v.y), pack_bf16(v.z, v.w));
    }
}

// ---------------------------------------------------------------------------
// GroupNorm: fp32 in -> bf16 out (same [C][N] layout)
// ---------------------------------------------------------------------------
__global__ __launch_bounds__(256) void groupnorm_kernel(
    const float* __restrict__ x, const float* __restrict__ w,
    const float* __restrict__ b, __nv_bfloat16* __restrict__ out)
{
    const int CPG = CCH / NGRP;
    const int GSZ = CPG * NPIX;
    int bg = blockIdx.x;
    int batch = bg / NGRP, g = bg % NGRP;
    size_t base = (size_t)batch * CCH * NPIX + (size_t)g * CPG * NPIX;
    const float4* x4 = (const float4*)(x + base);
    uint2* o2 = (uint2*)(out + base);
    int tid = threadIdx.x;

    float s = 0.f, ss = 0.f;
    for (int i = tid; i < GSZ / 4; i += 256) {
        float4 v = x4[i];
        s  += v.x + v.y + v.z + v.w;
        ss += v.x * v.x + v.y * v.y + v.z * v.z + v.w * v.w;
    }
    __shared__ float rs[8], rss[8];
    float ws = warpSum(s), wss = warpSum(ss);
    int lane = tid & 31, wid = tid >> 5;
    if (lane == 0) { rs[wid] = ws; rss[wid] = wss; }
    __syncthreads();
    __shared__ float s_mean, s_inv;
    if (tid == 0) {
        float S = 0.f, SS = 0.f;
        #pragma unroll
        for (int i = 0; i < 8; i++) { S += rs[i]; SS += rss[i]; }
        float mean = S / (float)GSZ;
        float var = SS / (float)GSZ - mean * mean;
        s_mean = mean;
        s_inv = rsqrtf(var + EPSV);
    }
    __syncthreads();
    float mean = s_mean, inv = s_inv;

    for (int i = tid; i < GSZ / 4; i += 256) {
        int c = g * CPG + ((i * 4) / NPIX);
        float sc = w[c] * inv;
        float sb = b[c] - mean * sc;
        float4 v = x4[i];
        v.x = v.x * sc + sb; v.y = v.y * sc + sb;
        v.z = v.z * sc + sb; v.w = v.w * sc + sb;
        o2[i] = make_uint2(pack_bf16(v.x, v.y), pack_bf16(v.z, v.w));
    }
}

// ---------------------------------------------------------------------------
// Row softmax: fp32 scores in -> bf16 attn out
// ---------------------------------------------------------------------------
__global__ __launch_bounds__(256) void softmax_kernel(
    const float* __restrict__ s, __nv_bfloat16* __restrict__ a)
{
    size_t row = blockIdx.x;
    const float4* p = (const float4*)(s + row * NPIX);
    uint2* o2 = (uint2*)(a + row * NPIX);
    int tid = threadIdx.x;
    float4 r[4];
    float m = -1e30f;
    #pragma unroll
    for (int i = 0; i < 4; i++) {
        r[i] = p[tid + i * 256];
        m = fmaxf(m, fmaxf(fmaxf(r[i].x, r[i].y), fmaxf(r[i].z, r[i].w)));
    }
    __shared__ float red[8];
    float wm = warpMax(m);
    int lane = tid & 31, wid = tid >> 5;
    if (lane == 0) red[wid] = wm;
    __syncthreads();
    __shared__ float s_m, s_inv;
    if (tid == 0) {
        float mm = red[0];
        #pragma unroll
        for (int i = 1; i < 8; i++) mm = fmaxf(mm, red[i]);
        s_m = mm;
    }
    __syncthreads();
    m = s_m;
    float sum = 0.f;
    #pragma unroll
    for (int i = 0; i < 4; i++) {
        r[i].x = expf(r[i].x - m); r[i].y = expf(r[i].y - m);
        r[i].z = expf(r[i].z - m); r[i].w = expf(r[i].w - m);
        sum += r[i].x + r[i].y + r[i].z + r[i].w;
    }
    float wsum = warpSum(sum);
    if (lane == 0) red[wid] = wsum;
    __syncthreads();
    if (tid == 0) {
        float S = 0.f;
        #pragma unroll
        for (int i = 0; i < 8; i++) S += red[i];
        s_inv = 1.f / S;
    }
    __syncthreads();
    float inv = s_inv;
    #pragma unroll
    for (int i = 0; i < 4; i++) {
        o2[tid + i * 256] = make_uint2(pack_bf16(r[i].x * inv, r[i].y * inv),
                                       pack_bf16(r[i].z * inv, r[i].w * inv));
    }
}

// ---------------------------------------------------------------------------
// BF16 tensor-core GEMM, 4-stage cp.async pipeline (depth 3, ONE barrier/iter):
//   C[m,n] = alpha * sum_k A(m,k)*B(k,n)  (+bias[m]) (+resid)
//   TA==0: A(m,k)=A[m*lda+k]   TA==1: A(m,k)=A[k*lda+m]
//   TB==0: B(k,n)=B[k*ldb+n]   TB==1: B(k,n)=B[n*ldb+k]
//   OBF: output bf16 (else fp32)
// Block 128x128, BK=32, 256 threads (8 warps, warp tile 64x32).
// smem (halves): k-contig tiles [128][32] stride 40; m/n-contig [32][128]
// stride 136 (layouts identical to the verified R5 kernel).
// Dynamic smem: 4 stages x (10240 + 10240) B = 80 KB.
// ---------------------------------------------------------------------------
#define BM 128
#define BN 128
#define BK 32
#define STAGES 4
#define TILE_H 5120                     // halves per operand tile
#define SMEMSZ (STAGES * TILE_H * 2 * 2)  // 81920 bytes

#define MMA_BF16(d, a, b)                                                     \
    asm volatile(                                                             \
        "mma.sync.aligned.m16n8k16.row.col.f32.bf16.bf16.f32 "                \
        "{%0,%1,%2,%3},{%4,%5,%6,%7},{%8,%9},{%0,%1,%2,%3};"                  \
        : "+f"(d[0]), "+f"(d[1]), "+f"(d[2]), "+f"(d[3])                      \
        : "r"(a[0]), "r"(a[1]), "r"(a[2]), "r"(a[3]), "r"(b[0]), "r"(b[1]))

template<int TA, int TB, bool BIAS, bool RES, bool OBF>
__global__ __launch_bounds__(256) void bgemm_kernel(
    const __nv_bfloat16* __restrict__ A, int lda, size_t sA,
    const __nv_bfloat16* __restrict__ B, int ldb, size_t sB,
    void* __restrict__ Cv, int ldc, size_t sC,
    const float* __restrict__ bias,
    const float* __restrict__ resid, size_t sR,
    int K, float alpha)
{
    extern __shared__ __align__(16) uint16_t dsm[];
    uint16_t* Asm = dsm;                       // STAGES * TILE_H
    uint16_t* Bsm = dsm + STAGES * TILE_H;

    int bz = blockIdx.z;
    A += (size_t)bz * sA;
    B += (size_t)bz * sB;
    if (RES) resid += (size_t)bz * sR;

    const int m0 = blockIdx.y * BM;
    const int n0 = blockIdx.x * BN;
    const int tid = threadIdx.x;
    const int lane = tid & 31;
    const int warp = tid >> 5;
    const int wm = warp >> 2;          // 0..1
    const int wn = warp & 3;           // 0..3
    const int R  = wm * 64;
    const int CN = wn * 32;

    const uint32_t aS0 = (uint32_t)__cvta_generic_to_shared(Asm);
    const uint32_t bS0 = (uint32_t)__cvta_generic_to_shared(Bsm);

    // ---- staging: 2 x 16B chunks per operand per thread (tile = 8192B data) ----
    size_t gA[2]; int soA[2];
    size_t gB[2]; int soB[2];
    #pragma unroll
    for (int t = 0; t < 2; t++) {
        int f = tid + t * 256;                 // 0..511 chunks
        if (TA == 0) {                         // [128][32] k-contig, stride 40
            int m = f >> 2, c8 = (f & 3) << 3;
            gA[t] = (size_t)(m0 + m) * lda + c8;
            soA[t] = m * 40 + c8;
        } else {                               // [32][128] m-contig, stride 136
            int k = f >> 4, c8 = (f & 15) << 3;
            gA[t] = (size_t)k * lda + m0 + c8;
            soA[t] = k * 136 + c8;
        }
        if (TB == 0) {                         // [32][128] n-contig, stride 136
            int k = f >> 4, c8 = (f & 15) << 3;
            gB[t] = (size_t)k * ldb + n0 + c8;
            soB[t] = k * 136 + c8;
        } else {                               // [128][32] k-contig, stride 40
            int n = f >> 2, c8 = (f & 3) << 3;
            gB[t] = (size_t)(n0 + n) * ldb + c8;
            soB[t] = n * 40 + c8;
        }
    }
    const size_t stepA = (TA == 0) ? (size_t)BK : (size_t)BK * lda;
    const size_t stepB = (TB == 0) ? (size_t)BK * ldb : (size_t)BK;

    // ---- lane-derived LDSM base offsets (halves) ----
    const int lq = lane & 7;
    const int b1 = (lane >> 3) & 1;
    const int b2 = lane >> 4;
    int aBase, bBase;
    if (TA == 0) aBase = (R + lq + 8 * b1) * 40 + 8 * b2;
    else         aBase = (lq + 8 * b2) * 136 + R + 8 * b1;
    if (TB == 0) bBase = (lq + 8 * b1) * 136 + CN + 8 * b2;
    else         bBase = (CN + lq + 8 * b2) * 40 + 8 * b1;

    float acc[4][4][4];
    #pragma unroll
    for (int i = 0; i < 4; i++)
        #pragma unroll
        for (int j = 0; j < 4; j++)
            #pragma unroll
            for (int r = 0; r < 4; r++) acc[i][j][r] = 0.f;

    const int KT = K / BK;

    // ---- prologue: async-stage tiles 0..2 ----
    #pragma unroll
    for (int s = 0; s < 3; s++) {
        #pragma unroll
        for (int t = 0; t < 2; t++) {
            cpasync16(aS0 + (s * TILE_H + soA[t]) * 2, A + gA[t] + (size_t)s * stepA);
            cpasync16(bS0 + (s * TILE_H + soB[t]) * 2, B + gB[t] + (size_t)s * stepB);
        }
        CP_COMMIT();
    }

    for (int kt = 0; kt < KT; kt++) {
        const int cur = kt & 3;
        {
            const int rem = KT - 1 - kt;       // groups committed after stage kt
            if (rem >= 2)      asm volatile("cp.async.wait_group 2;");
            else if (rem == 1) asm volatile("cp.async.wait_group 1;");
            else               asm volatile("cp.async.wait_group 0;");
        }
        __syncthreads();

        const uint32_t aS = aS0 + cur * (TILE_H * 2);
        const uint32_t bS = bS0 + cur * (TILE_H * 2);
        #pragma unroll
        for (int ks = 0; ks < 2; ks++) {
            uint32_t a[4][4], b[4][2];
            #pragma unroll
            for (int mt = 0; mt < 4; mt++) {
                int off = (TA == 0) ? (aBase + mt * 640 + ks * 16)
                                    : (aBase + ks * 2176 + mt * 16);
                uint32_t addr = aS + 2 * off;
                if (TA == 0) ldsm4 (a[mt][0], a[mt][1], a[mt][2], a[mt][3], addr);
                else         ldsm4t(a[mt][0], a[mt][1], a[mt][2], a[mt][3], addr);
            }
            #pragma unroll
            for (int ntp = 0; ntp < 2; ntp++) {
                int off = (TB == 0) ? (bBase + ks * 2176 + ntp * 16)
                                    : (bBase + ntp * 640 + ks * 16);
                uint32_t addr = bS + 2 * off;
                if (TB == 0)
                    ldsm4t(b[ntp*2][0], b[ntp*2][1], b[ntp*2+1][0], b[ntp*2+1][1], addr);
                else
                    ldsm4 (b[ntp*2][0], b[ntp*2][1], b[ntp*2+1][0], b[ntp*2+1][1], addr);
            }
            #pragma unroll
            for (int mt = 0; mt < 4; mt++)
                #pragma unroll
                for (int nt = 0; nt < 4; nt++)
                    MMA_BF16(acc[mt][nt], a[mt], b[nt]);
        }

        // issue stage kt+3 into buffer (kt+3)&3 — consumed at iter kt-1,
        // protected by this iteration's top barrier. No second barrier needed.
        if (kt + 3 < KT) {
            const int nxt = (kt + 3) & 3;
            size_t ko = (size_t)(kt + 3);
            #pragma unroll
            for (int t = 0; t < 2; t++) {
                cpasync16(aS0 + (nxt * TILE_H + soA[t]) * 2, A + gA[t] + ko * stepA);
                cpasync16(bS0 + (nxt * TILE_H + soB[t]) * 2, B + gB[t] + ko * stepB);
            }
            CP_COMMIT();
        }
    }

    // ---- epilogue ----
    #pragma unroll
    for (int mt = 0; mt < 4; mt++) {
        int mA = m0 + R + mt * 16 + (lane >> 2);
        #pragma unroll
        for (int h = 0; h < 2; h++) {
            int m = mA + h * 8;
            float bi = BIAS ? bias[m] : 0.f;
            #pragma unroll
            for (int nt = 0; nt < 4; nt++) {
                int n = n0 + CN + nt * 8 + 2 * (lane & 3);
                size_t off = (size_t)m * ldc + n;
                float ox = acc[mt][nt][h * 2 + 0] * alpha + bi;
                float oy = acc[mt][nt][h * 2 + 1] * alpha + bi;
                if (OBF) {
                    __nv_bfloat16* Cb = (__nv_bfloat16*)Cv + (size_t)bz * sC;
                    *(uint32_t*)(Cb + off) = pack_bf16(ox, oy);
                } else {
                    float* Cf = (float*)Cv + (size_t)bz * sC;
                    if (RES) {
                        float2 rr = *(const float2*)(resid + off);
                        ox += rr.x; oy += rr.y;
                    }
                    float2 o2 = make_float2(ox, oy);
                    *(float2*)(Cf + off) = o2;
                }
            }
        }
    }
}

// ---------------------------------------------------------------------------
// Host launcher
// ---------------------------------------------------------------------------
extern "C" void kernel_launch(void* const* d_in, const int* in_sizes, int n_in,
                              void* d_out, int out_size)
{
    const float* x      = (const float*)d_in[0];
    const float* norm_w = (const float*)d_in[1];
    const float* norm_b = (const float*)d_in[2];
    const float* wq     = (const float*)d_in[3];
    const float* bq     = (const float*)d_in[4];
    const float* wk     = (const float*)d_in[5];
    const float* bk     = (const float*)d_in[6];
    const float* wv     = (const float*)d_in[7];
    const float* bv     = (const float*)d_in[8];
    const float* wo     = (const float*)d_in[9];
    const float* bo     = (const float*)d_in[10];
    float* out = (float*)d_out;

    __nv_bfloat16 *wb, *hb, *qb, *kb, *vb, *ab, *aob;
    float* s;
    cudaGetSymbolAddress((void**)&wb,  g_wb);
    cudaGetSymbolAddress((void**)&hb,  g_hb);
    cudaGetSymbolAddress((void**)&qb,  g_qb);
    cudaGetSymbolAddress((void**)&kb,  g_kb);
    cudaGetSymbolAddress((void**)&vb,  g_vb);
    cudaGetSymbolAddress((void**)&ab,  g_ab);
    cudaGetSymbolAddress((void**)&aob, g_aob);
    cudaGetSymbolAddress((void**)&s,   g_s);
    __nv_bfloat16* wqb = wb;
    __nv_bfloat16* wkb = wb + (size_t)CCH * CCH;
    __nv_bfloat16* wvb = wb + (size_t)2 * CCH * CCH;
    __nv_bfloat16* wob = wb + (size_t)3 * CCH * CCH;

    const size_t CN = (size_t)CCH * NPIX;
    const size_t NN = (size_t)NPIX * NPIX;
    const float scale = 1.0f / sqrtf((float)CCH);

    // dynamic smem limit for all four instantiations (host-side, idempotent)
    cudaFuncSetAttribute(bgemm_kernel<0, 0, true,  false, true >,
                         cudaFuncAttributeMaxDynamicSharedMemorySize, SMEMSZ);
    cudaFuncSetAttribute(bgemm_kernel<1, 0, false, false, false>,
                         cudaFuncAttributeMaxDynamicSharedMemorySize, SMEMSZ);
    cudaFuncSetAttribute(bgemm_kernel<0, 1, false, false, true >,
                         cudaFuncAttributeMaxDynamicSharedMemorySize, SMEMSZ);
    cudaFuncSetAttribute(bgemm_kernel<0, 0, true,  true,  false>,
                         cudaFuncAttributeMaxDynamicSharedMemorySize, SMEMSZ);

    // 0. weights -> bf16
    cvtw_kernel<<<512, 256>>>(wq, wk, wv, wo, wb);

    // 1. GroupNorm -> bf16 h
    groupnorm_kernel<<<BATCH * NGRP, 256>>>(x, norm_w, norm_b, hb);

    // 2. q/k/v projections: W[512,512] @ h[512,4096] -> bf16
    dim3 gProj(NPIX / BN, CCH / BM, BATCH);
    bgemm_kernel<0, 0, true, false, true><<<gProj, 256, SMEMSZ>>>(
        wqb, CCH, 0, hb, NPIX, CN, qb, NPIX, CN, bq, nullptr, 0, CCH, 1.0f);
    bgemm_kernel<0, 0, true, false, true><<<gProj, 256, SMEMSZ>>>(
        wkb, CCH, 0, hb, NPIX, CN, kb, NPIX, CN, bk, nullptr, 0, CCH, 1.0f);
    bgemm_kernel<0, 0, true, false, true><<<gProj, 256, SMEMSZ>>>(
        wvb, CCH, 0, hb, NPIX, CN, vb, NPIX, CN, bv, nullptr, 0, CCH, 1.0f);

    // 3. scores = scale * q^T k  (fp32 out; M=N=4096, K=512)
    dim3 gScore(NPIX / BN, NPIX / BM, BATCH);
    bgemm_kernel<1, 0, false, false, false><<<gScore, 256, SMEMSZ>>>(
        qb, NPIX, CN, kb, NPIX, CN, s, NPIX, NN, nullptr, nullptr, 0, CCH, scale);

    // 4. softmax rows -> bf16 attn
    softmax_kernel<<<BATCH * NPIX, 256>>>(s, ab);

    // 5. ao[c,i] = sum_j v[c,j] attn[i,j]  (M=512, N=4096, K=4096) -> bf16
    dim3 gOut(NPIX / BN, CCH / BM, BATCH);
    bgemm_kernel<0, 1, false, false, true><<<gOut, 256, SMEMSZ>>>(
        vb, NPIX, CN, ab, NPIX, NN, aob, NPIX, CN, nullptr, nullptr, 0, NPIX, 1.0f);

    // 6. out = x + wo @ ao + bo  (fp32 out + residual)
    bgemm_kernel<0, 0, true, true, false><<<gOut, 256, SMEMSZ>>>(
        wob, CCH, 0, aob, NPIX, CN, out, NPIX, CN, bo, x, CN, CCH, 1.0f);
}